// round 17
// baseline (speedup 1.0000x reference)
#include <cuda_runtime.h>
#include <math.h>

#define ML    1025
#define HW2   525312
#define NGG   131072
#define GNN_N (ML*ML)        // 1050625
#define MHH   3072
#define LR_N  (MHH*MHH)      // 9437184
#define PI_D  3.14159265358979323846

typedef float2 cf;
typedef unsigned long long u64;

__device__ __forceinline__ cf cmk(float x, float y){ return make_float2(x,y); }
__device__ __forceinline__ cf cadd(cf a, cf b){ return cmk(a.x+b.x, a.y+b.y); }
__device__ __forceinline__ cf cmul(cf a, cf b){ return cmk(a.x*b.x - a.y*b.y, a.x*b.y + a.y*b.x); }
__device__ __forceinline__ cf cfma_(cf a, cf b, cf acc){
    acc.x = fmaf(a.x, b.x, fmaf(-a.y, b.y, acc.x));
    acc.y = fmaf(a.x, b.y, fmaf( a.y, b.x, acc.y));
    return acc;
}
__device__ __forceinline__ cf crelu(cf a){ return cmk(fmaxf(a.x,0.f), fmaxf(a.y,0.f)); }
__device__ __forceinline__ cf conj2(cf a){ return cmk(a.x, -a.y); }

// ---- packed f32x2 helpers ---------------------------------------------------
__device__ __forceinline__ u64 pk2(float lo, float hi){
    u64 r; asm("mov.b64 %0, {%1, %2};" : "=l"(r) : "f"(lo), "f"(hi)); return r;
}
__device__ __forceinline__ void up2(u64 v, float &lo, float &hi){
    asm("mov.b64 {%0, %1}, %2;" : "=f"(lo), "=f"(hi) : "l"(v));
}
__device__ __forceinline__ u64 f2fma(u64 a, u64 b, u64 c){
    u64 r; asm("fma.rn.f32x2 %0, %1, %2, %3;" : "=l"(r) : "l"(a), "l"(b), "l"(c)); return r;
}

// ---------------- scratch (static device arrays; no runtime alloc) ----------
__device__ cf    g_Xf  [HW2*16];
__device__ cf    g_Xtv [HW2*16];
__device__ cf    g_spec[GNN_N];
__device__ cf    g_C   [GNN_N];
__device__ float g_gnn [GNN_N];
__device__ float g_X   [GNN_N];
__device__ float g_tmp [GNN_N];
__device__ float g_D   [GNN_N];
__device__ float g_diff[GNN_N];     // gnn - X (current), feeds box1

// ---------------- diagnostic no-op to steer ncu's fixed launch slot ---------
__global__ void k_nop(){}

// ---------------- Stage A: per-element input MLP ----------------------------
__global__ void k_stageA(const float* __restrict__ xr, const float* __restrict__ xi,
                         const cf* __restrict__ fw0, const cf* __restrict__ fb0,
                         const cf* __restrict__ fw1, const cf* __restrict__ fb1,
                         const cf* __restrict__ lw,  const cf* __restrict__ lb)
{
    __shared__ cf s_fw0[16], s_fb0[16], s_fw1[256], s_fb1[16], s_lw[16], s_lb[16];
    int tid = threadIdx.x;
    if (tid < 16){ s_fw0[tid]=fw0[tid]; s_fb0[tid]=fb0[tid]; s_fb1[tid]=fb1[tid];
                   s_lw[tid]=lw[tid];   s_lb[tid]=lb[tid]; }
    for (int i = tid; i < 256; i += blockDim.x) s_fw1[i] = fw1[i];
    __syncthreads();
    int n = blockIdx.x * blockDim.x + tid;
    if (n >= HW2) return;
    cf x0 = cmk(xr[n], xi[n]);
    cf h[16], o16[16];
#pragma unroll
    for (int c = 0; c < 16; c++) h[c] = crelu(cfma_(x0, s_fw0[c], s_fb0[c]));
#pragma unroll
    for (int o = 0; o < 16; o++){
        cf acc = s_fb1[o];
#pragma unroll
        for (int c = 0; c < 16; c++) acc = cfma_(h[c], s_fw1[c*16+o], acc);
        acc = cadd(acc, cfma_(x0, s_lw[o], s_lb[o]));
        o16[o] = crelu(acc);
    }
    float4* dst = reinterpret_cast<float4*>(&g_Xf[(size_t)n*16]);
#pragma unroll
    for (int q = 0; q < 8; q++){
        dst[q] = make_float4(o16[2*q].x, o16[2*q].y, o16[2*q+1].x, o16[2*q+1].y);
    }
}

// ---------------- Stage B: GNN gather + hierarchical permutation ------------
__global__ void k_stageB(const cf* __restrict__ gnn_w, const int* __restrict__ NI,
                         const int* __restrict__ hmask, const int* __restrict__ hind)
{
    int j = blockIdx.x * blockDim.x + threadIdx.x;
    if (j >= HW2) return;
    int idx = hind[j];
    float4* dst = reinterpret_cast<float4*>(&g_Xtv[(size_t)j*16]);
    if (idx < NGG){
        cf acc[16];
#pragma unroll
        for (int c = 0; c < 16; c++) acc[c] = cmk(0.f,0.f);
#pragma unroll 1
        for (int k = 0; k < 8; k++){
            cf w = gnn_w[k*NGG+idx];
            int src = NI[(k+1)*NGG+idx];
            const float4* nb = reinterpret_cast<const float4*>(&g_Xf[(size_t)src*16]);
#pragma unroll
            for (int q = 0; q < 8; q++){
                float4 v = nb[q];
                acc[2*q]   = cfma_(cmk(v.x,v.y), w, acc[2*q]);
                acc[2*q+1] = cfma_(cmk(v.z,v.w), w, acc[2*q+1]);
            }
        }
#pragma unroll
        for (int q = 0; q < 8; q++)
            dst[q] = make_float4(acc[2*q].x, acc[2*q].y, acc[2*q+1].x, acc[2*q+1].y);
    } else {
        int src = hmask[idx - NGG];
        const float4* nb = reinterpret_cast<const float4*>(&g_Xf[(size_t)src*16]);
#pragma unroll
        for (int q = 0; q < 8; q++) dst[q] = nb[q];
    }
}

// ---------------- Stage C: lane-pair split, E=2 elements per thread ---------
// Lanes 2i/2i+1 co-own elements n0=base+2i*? ... (pair p handles n0, n0+1).
// Each thread owns outputs/slots [half*8, half*8+8) of every 16-vector, for
// BOTH elements. Weight LDS.128 loads amortize over the two elements.
__device__ __forceinline__ cf gfun(int t){
    float ph = (float)(t - 512) * (float)(2.0 * PI_D / 1025.0);
    float s, c; sincosf(ph, &s, &c);
    return cmk(1.f - c, s);
}

// dual-element half-output matvec:
// oE[o] = (relu?)( Bv8[o] + sum_c xE_full[c] * W[c][half*8+o] ) for E in {0,1}
__device__ __forceinline__ void mv8e2(const ulonglong2* __restrict__ Wp,
                                      const cf* __restrict__ Bv8,
                                      const cf* __restrict__ x0, const cf* __restrict__ x1,
                                      cf* __restrict__ o0, cf* __restrict__ o1,
                                      bool relu, int half)
{
    u64 aA0[8], aB0[8], aA1[8], aB1[8];
#pragma unroll
    for (int o = 0; o < 8; o++){
        aA0[o] = pk2(Bv8[o].x, Bv8[o].y);  aB0[o] = pk2(0.f, 0.f);
        aA1[o] = pk2(Bv8[o].x, Bv8[o].y);  aB1[o] = pk2(0.f, 0.f);
    }
    const int jb = half*4;
    // pass 1: own-half inputs (c = half*8 + j)
#pragma unroll
    for (int j = 0; j < 8; j++){
        int c = half*8 + j;
        u64 ax0 = pk2(x0[j].x, x0[j].x), ay0 = pk2(x0[j].y, x0[j].y);
        u64 ax1 = pk2(x1[j].x, x1[j].x), ay1 = pk2(x1[j].y, x1[j].y);
#pragma unroll
        for (int jj = 0; jj < 4; jj++){
            ulonglong2 w = Wp[c*8 + jb + jj];
            aA0[2*jj]   = f2fma(ax0, w.x, aA0[2*jj]);
            aB0[2*jj]   = f2fma(ay0, w.x, aB0[2*jj]);
            aA0[2*jj+1] = f2fma(ax0, w.y, aA0[2*jj+1]);
            aB0[2*jj+1] = f2fma(ay0, w.y, aB0[2*jj+1]);
            aA1[2*jj]   = f2fma(ax1, w.x, aA1[2*jj]);
            aB1[2*jj]   = f2fma(ay1, w.x, aB1[2*jj]);
            aA1[2*jj+1] = f2fma(ax1, w.y, aA1[2*jj+1]);
            aB1[2*jj+1] = f2fma(ay1, w.y, aB1[2*jj+1]);
        }
    }
    // pass 2: partner-half inputs via shfl (c = (1-half)*8 + j)
#pragma unroll
    for (int j = 0; j < 8; j++){
        int c = (half^1)*8 + j;
        float p0x = __shfl_xor_sync(0xffffffffu, x0[j].x, 1);
        float p0y = __shfl_xor_sync(0xffffffffu, x0[j].y, 1);
        float p1x = __shfl_xor_sync(0xffffffffu, x1[j].x, 1);
        float p1y = __shfl_xor_sync(0xffffffffu, x1[j].y, 1);
        u64 ax0 = pk2(p0x, p0x), ay0 = pk2(p0y, p0y);
        u64 ax1 = pk2(p1x, p1x), ay1 = pk2(p1y, p1y);
#pragma unroll
        for (int jj = 0; jj < 4; jj++){
            ulonglong2 w = Wp[c*8 + jb + jj];
            aA0[2*jj]   = f2fma(ax0, w.x, aA0[2*jj]);
            aB0[2*jj]   = f2fma(ay0, w.x, aB0[2*jj]);
            aA0[2*jj+1] = f2fma(ax0, w.y, aA0[2*jj+1]);
            aB0[2*jj+1] = f2fma(ay0, w.y, aB0[2*jj+1]);
            aA1[2*jj]   = f2fma(ax1, w.x, aA1[2*jj]);
            aB1[2*jj]   = f2fma(ay1, w.x, aB1[2*jj]);
            aA1[2*jj+1] = f2fma(ax1, w.y, aA1[2*jj+1]);
            aB1[2*jj+1] = f2fma(ay1, w.y, aB1[2*jj+1]);
        }
    }
#pragma unroll
    for (int o = 0; o < 8; o++){
        float alo, ahi, blo, bhi;
        up2(aA0[o], alo, ahi); up2(aB0[o], blo, bhi);
        float ox = alo - bhi, oy = ahi + blo;
        o0[o] = relu ? cmk(fmaxf(ox,0.f), fmaxf(oy,0.f)) : cmk(ox, oy);
        up2(aA1[o], alo, ahi); up2(aB1[o], blo, bhi);
        ox = alo - bhi; oy = ahi + blo;
        o1[o] = relu ? cmk(fmaxf(ox,0.f), fmaxf(oy,0.f)) : cmk(ox, oy);
    }
}

// HPE[o] += sum_c xE_full[c] * W[c][half*8+o]
__device__ __forceinline__ void mv8e2_add(const ulonglong2* __restrict__ Wp,
                                          const cf* __restrict__ x0, const cf* __restrict__ x1,
                                          cf* __restrict__ H0, cf* __restrict__ H1, int half)
{
    u64 aA0[8], aB0[8], aA1[8], aB1[8];
#pragma unroll
    for (int o = 0; o < 8; o++){
        aA0[o] = pk2(0.f,0.f); aB0[o] = pk2(0.f,0.f);
        aA1[o] = pk2(0.f,0.f); aB1[o] = pk2(0.f,0.f);
    }
    const int jb = half*4;
#pragma unroll
    for (int j = 0; j < 8; j++){
        int c = half*8 + j;
        u64 ax0 = pk2(x0[j].x, x0[j].x), ay0 = pk2(x0[j].y, x0[j].y);
        u64 ax1 = pk2(x1[j].x, x1[j].x), ay1 = pk2(x1[j].y, x1[j].y);
#pragma unroll
        for (int jj = 0; jj < 4; jj++){
            ulonglong2 w = Wp[c*8 + jb + jj];
            aA0[2*jj]   = f2fma(ax0, w.x, aA0[2*jj]);
            aB0[2*jj]   = f2fma(ay0, w.x, aB0[2*jj]);
            aA0[2*jj+1] = f2fma(ax0, w.y, aA0[2*jj+1]);
            aB0[2*jj+1] = f2fma(ay0, w.y, aB0[2*jj+1]);
            aA1[2*jj]   = f2fma(ax1, w.x, aA1[2*jj]);
            aB1[2*jj]   = f2fma(ay1, w.x, aB1[2*jj]);
            aA1[2*jj+1] = f2fma(ax1, w.y, aA1[2*jj+1]);
            aB1[2*jj+1] = f2fma(ay1, w.y, aB1[2*jj+1]);
        }
    }
#pragma unroll
    for (int j = 0; j < 8; j++){
        int c = (half^1)*8 + j;
        float p0x = __shfl_xor_sync(0xffffffffu, x0[j].x, 1);
        float p0y = __shfl_xor_sync(0xffffffffu, x0[j].y, 1);
        float p1x = __shfl_xor_sync(0xffffffffu, x1[j].x, 1);
        float p1y = __shfl_xor_sync(0xffffffffu, x1[j].y, 1);
        u64 ax0 = pk2(p0x, p0x), ay0 = pk2(p0y, p0y);
        u64 ax1 = pk2(p1x, p1x), ay1 = pk2(p1y, p1y);
#pragma unroll
        for (int jj = 0; jj < 4; jj++){
            ulonglong2 w = Wp[c*8 + jb + jj];
            aA0[2*jj]   = f2fma(ax0, w.x, aA0[2*jj]);
            aB0[2*jj]   = f2fma(ay0, w.x, aB0[2*jj]);
            aA0[2*jj+1] = f2fma(ax0, w.y, aA0[2*jj+1]);
            aB0[2*jj+1] = f2fma(ay0, w.y, aB0[2*jj+1]);
            aA1[2*jj]   = f2fma(ax1, w.x, aA1[2*jj]);
            aB1[2*jj]   = f2fma(ay1, w.x, aB1[2*jj]);
            aA1[2*jj+1] = f2fma(ax1, w.y, aA1[2*jj+1]);
            aB1[2*jj+1] = f2fma(ay1, w.y, aB1[2*jj+1]);
        }
    }
#pragma unroll
    for (int o = 0; o < 8; o++){
        float alo, ahi, blo, bhi;
        up2(aA0[o], alo, ahi); up2(aB0[o], blo, bhi);
        H0[o].x += alo - bhi;  H0[o].y += ahi + blo;
        up2(aA1[o], alo, ahi); up2(aB1[o], blo, bhi);
        H1[o].x += alo - bhi;  H1[o].y += ahi + blo;
    }
}

// dynamic shared layout:
//  [0, 32768)          : u64 Wd[4096]  (EW1 0, EW2 768, LW1 1536, LW2 2304, MW1 3072, MW2 3840)
//  [32768, +241cf)     : cf biases[241]: EB1 0, EB2 48, LB1 96, LB2 144, MB1 192, MB2 208, MW3 224, MB3 240
#define SC_SMEM (32768 + 256*8)

// 128 threads = 64 pairs = 128 elements/block; HW2 = 128 * 4104 exactly.
__global__ __launch_bounds__(128, 2)
void k_stageC(const cf* __restrict__ ew1, const cf* __restrict__ eb1,
              const cf* __restrict__ ew2, const cf* __restrict__ eb2,
              const cf* __restrict__ lw1, const cf* __restrict__ lb1,
              const cf* __restrict__ lw2, const cf* __restrict__ lb2,
              const cf* __restrict__ mw1, const cf* __restrict__ mb1,
              const cf* __restrict__ mw2, const cf* __restrict__ mb2,
              const cf* __restrict__ mw3, const cf* __restrict__ mb3,
              const float* __restrict__ aver_r, const float* __restrict__ aver_i,
              float c0, float s0, float c1, float s1, float c2, float s2)
{
    extern __shared__ char sraw[];
    u64* Wd = (u64*)sraw;
    cf* BI = (cf*)(sraw + 32768);
    int tid = threadIdx.x;

    const u64* e1u = (const u64*)ew1;  const u64* e2u = (const u64*)ew2;
    const u64* l1u = (const u64*)lw1;  const u64* l2u = (const u64*)lw2;
    const u64* m1u = (const u64*)mw1;  const u64* m2u = (const u64*)mw2;
    for (int i = tid; i < 768; i += blockDim.x){
        Wd[i]       = e1u[i];
        Wd[768+i]   = e2u[i];
        Wd[1536+i]  = l1u[i];
        Wd[2304+i]  = l2u[i];
        Wd[3072+i]  = m1u[i];
    }
    for (int i = tid; i < 256; i += blockDim.x) Wd[3840+i] = m2u[i];
    if (tid < 48){ BI[tid]=eb1[tid]; BI[48+tid]=eb2[tid]; BI[96+tid]=lb1[tid]; BI[144+tid]=lb2[tid]; }
    if (tid < 16){ BI[192+tid]=mb1[tid]; BI[208+tid]=mb2[tid]; BI[224+tid]=mw3[tid]; }
    if (tid == 0) BI[240] = mb3[0];
    __syncthreads();

    const int half = tid & 1;
    const int n0 = blockIdx.x * 128 + (tid >> 1) * 2;   // pair handles n0, n0+1
    const int n1 = n0 + 1;
    int yy0 = n0 / ML, xx0 = n0 - yy0 * ML;
    int yy1 = n1 / ML, xx1 = n1 - yy1 * ML;
    float dy0 = (float)yy0 - 512.f, dx0 = (float)xx0 - 512.f;
    float dy1 = (float)yy1 - 512.f, dx1 = (float)xx1 - 512.f;

    float cth[3] = {c0, c1, c2}, sth[3] = {s0, s1, s2};
    cf A0[8], A1[8], Bt0[8], Bt1[8], T0[8], T1[8], H0[8], H1[8];
#pragma unroll
    for (int o = 0; o < 8; o++){ H0[o] = BI[192 + half*8 + o]; H1[o] = H0[o]; }

    const float4* Xt40 = reinterpret_cast<const float4*>(&g_Xtv[(size_t)n0*16 + half*8]);
    const float4* Xf40 = reinterpret_cast<const float4*>(&g_Xf [(size_t)n0*16 + half*8]);
    const float4* Xt41 = reinterpret_cast<const float4*>(&g_Xtv[(size_t)n1*16 + half*8]);
    const float4* Xf41 = reinterpret_cast<const float4*>(&g_Xf [(size_t)n1*16 + half*8]);

#pragma unroll 1
    for (int a = 0; a < 3; a++){
        // geometry for element 0
        float ys = fmaf(cth[a], dy0, fmaf( sth[a], dx0, 512.f));
        float xs = fmaf(-sth[a], dy0, fmaf(cth[a], dx0, 512.f));
        ys = fminf(fmaxf(ys, 0.f), 1024.f);
        xs = fminf(fmaxf(xs, 0.f), 1024.f);
        float y0f = floorf(ys), x0f = floorf(xs);
        int y0 = (int)y0f, x0 = (int)x0f;
        int y1i = min(y0+1, 1024), x1i = min(x0+1, 1024);
        float wy = ys - y0f, wx = xs - x0f;
        cf gxa = gfun(x0), gxb = gfun(x1i), gya = gfun(y0), gyb = gfun(y1i);
        cf tvx0 = cmk((1.f-wx)*gxa.x + wx*gxb.x, (1.f-wx)*gxa.y + wx*gxb.y);
        cf tvy0 = cmk((1.f-wy)*gya.x + wy*gyb.x, (1.f-wy)*gya.y + wy*gyb.y);
        float eig0 = tvx0.x*tvx0.x + tvx0.y*tvx0.y + tvy0.x*tvy0.x + tvy0.y*tvy0.y;
        // geometry for element 1
        ys = fmaf(cth[a], dy1, fmaf( sth[a], dx1, 512.f));
        xs = fmaf(-sth[a], dy1, fmaf(cth[a], dx1, 512.f));
        ys = fminf(fmaxf(ys, 0.f), 1024.f);
        xs = fminf(fmaxf(xs, 0.f), 1024.f);
        y0f = floorf(ys); x0f = floorf(xs);
        y0 = (int)y0f; x0 = (int)x0f;
        y1i = min(y0+1, 1024); x1i = min(x0+1, 1024);
        wy = ys - y0f; wx = xs - x0f;
        gxa = gfun(x0); gxb = gfun(x1i); gya = gfun(y0); gyb = gfun(y1i);
        cf tvx1 = cmk((1.f-wx)*gxa.x + wx*gxb.x, (1.f-wx)*gxa.y + wx*gxb.y);
        cf tvy1 = cmk((1.f-wy)*gya.x + wy*gyb.x, (1.f-wy)*gya.y + wy*gyb.y);
        float eig1 = tvx1.x*tvx1.x + tvx1.y*tvx1.y + tvy1.x*tvy1.x + tvy1.y*tvy1.y;

        const ulonglong2* W1 = (const ulonglong2*)(Wd + a*256);
        const ulonglong2* W2 = (const ulonglong2*)(Wd + 768 + a*256);
        const ulonglong2* L1 = (const ulonglong2*)(Wd + 1536 + a*256);
        const ulonglong2* L2 = (const ulonglong2*)(Wd + 2304 + a*256);
        const ulonglong2* WM = (const ulonglong2*)(Wd + 3072 + a*256);
        const cf* B1  = BI + a*16 + half*8;
        const cf* B2  = BI + 48 + a*16 + half*8;
        const cf* LB1 = BI + 96 + a*16 + half*8;
        const cf* LB2 = BI + 144 + a*16 + half*8;

        // x path: (Xtv * tvfftx) -> mlp2 -> * conj(tvfftx) -> crelu
#pragma unroll
        for (int q = 0; q < 4; q++){
            float4 v = Xt40[q];
            A0[2*q]   = cmul(cmk(v.x,v.y), tvx0);
            A0[2*q+1] = cmul(cmk(v.z,v.w), tvx0);
            float4 u = Xt41[q];
            A1[2*q]   = cmul(cmk(u.x,u.y), tvx1);
            A1[2*q+1] = cmul(cmk(u.z,u.w), tvx1);
        }
        mv8e2(W1, B1, A0, A1, Bt0, Bt1, true,  half);
        mv8e2(W2, B2, Bt0, Bt1, A0, A1, false, half);
        cf ctvx0 = conj2(tvx0), ctvx1 = conj2(tvx1);
#pragma unroll
        for (int o = 0; o < 8; o++){
            T0[o] = crelu(cmul(A0[o], ctvx0));
            T1[o] = crelu(cmul(A1[o], ctvx1));
        }
        // y path: (Xf * tvffty) -> mlp2 -> * conj(tvffty) -> crelu
#pragma unroll
        for (int q = 0; q < 4; q++){
            float4 v = Xf40[q];
            A0[2*q]   = cmul(cmk(v.x,v.y), tvy0);
            A0[2*q+1] = cmul(cmk(v.z,v.w), tvy0);
            float4 u = Xf41[q];
            A1[2*q]   = cmul(cmk(u.x,u.y), tvy1);
            A1[2*q+1] = cmul(cmk(u.z,u.w), tvy1);
        }
        mv8e2(W1, B1, A0, A1, Bt0, Bt1, true,  half);
        mv8e2(W2, B2, Bt0, Bt1, A0, A1, false, half);
        cf ctvy0 = conj2(tvy0), ctvy1 = conj2(tvy1);
#pragma unroll
        for (int o = 0; o < 8; o++){
            T0[o] = cadd(T0[o], crelu(cmul(A0[o], ctvy0)));
            T1[o] = cadd(T1[o], crelu(cmul(A1[o], ctvy1)));
        }
        // l path: mlp2(t) / eig -> crelu
        mv8e2(L1, LB1, T0, T1, Bt0, Bt1, true,  half);
        mv8e2(L2, LB2, Bt0, Bt1, A0, A1, false, half);
        float ie0 = 1.0f / eig0, ie1 = 1.0f / eig1;
#pragma unroll
        for (int o = 0; o < 8; o++){
            A0[o] = crelu(cmk(A0[o].x*ie0, A0[o].y*ie0));
            A1[o] = crelu(cmk(A1[o].x*ie1, A1[o].y*ie1));
        }
        // accumulate through this angle's 16-row block of mw1
        mv8e2_add(WM, A0, A1, H0, H1, half);
    }
#pragma unroll
    for (int o = 0; o < 8; o++){ A0[o] = crelu(H0[o]); A1[o] = crelu(H1[o]); }
    mv8e2((const ulonglong2*)(Wd + 3840), BI + 208 + half*8, A0, A1, Bt0, Bt1, true, half);
    // final 16->1 head: partial per half, combine across the pair
    cf z0 = cmk(0.f, 0.f), z1 = cmk(0.f, 0.f);
#pragma unroll
    for (int c = 0; c < 8; c++){
        z0 = cfma_(Bt0[c], BI[224 + half*8 + c], z0);
        z1 = cfma_(Bt1[c], BI[224 + half*8 + c], z1);
    }
    float o0x = z0.x + __shfl_xor_sync(0xffffffffu, z0.x, 1);
    float o0y = z0.y + __shfl_xor_sync(0xffffffffu, z0.y, 1);
    float o1x = z1.x + __shfl_xor_sync(0xffffffffu, z1.x, 1);
    float o1y = z1.y + __shfl_xor_sync(0xffffffffu, z1.y, 1);
    if (half == 0){
        cf zh0 = cadd(cmk(o0x, o0y), BI[240]);
        cf zh1 = cadd(cmk(o1x, o1y), BI[240]);
        g_spec[n0] = zh0;
        g_spec[2*HW2 - n0] = conj2(zh0);
        g_spec[n1] = zh1;
        g_spec[2*HW2 - n1] = conj2(zh1);
        if (n0 == 0) g_spec[HW2] = cmk(aver_r[0], aver_i[0]);
    }
}

// ---------------- mixed-radix (41x25) length-1025 inverse DFT ---------------
__global__ void k_dft_rows()
{
    __shared__ cf xs[1025], bs[1025], tw[1025], tw41[41], tw25[25];
    int tid = threadIdx.x;
    int u = blockIdx.x;
    int su = u + 512; if (su >= 1025) su -= 1025;
    for (int m = tid; m < 1025; m += blockDim.x){
        float ang = (float)((double)m * (2.0 * PI_D / 1025.0));
        float s, c; sincosf(ang, &s, &c);
        tw[m] = cmk(c, s);                 // e^{+2pi i m/1025}
        int sv = m + 512; if (sv >= 1025) sv -= 1025;
        xs[m] = g_spec[su*1025 + sv];
    }
    __syncthreads();
    if (tid < 41) tw41[tid] = tw[tid*25];
    if (tid < 25) tw25[tid] = tw[tid*41];
    __syncthreads();
    for (int idx = tid; idx < 1025; idx += blockDim.x){
        int k1 = idx % 41, n2 = idx / 41;
        cf acc = cmk(0.f,0.f);
        int m41 = 0;
        for (int n1 = 0; n1 < 41; n1++){
            acc = cfma_(xs[25*n1 + n2], tw41[m41], acc);
            m41 += k1; if (m41 >= 41) m41 -= 41;
        }
        bs[k1*25 + n2] = cmul(acc, tw[n2*k1]);
    }
    __syncthreads();
    for (int k = tid; k < 1025; k += blockDim.x){
        int k1 = k % 41, k2 = k / 41;
        cf acc = cmk(0.f,0.f);
        int m25 = 0;
        for (int n2 = 0; n2 < 25; n2++){
            acc = cfma_(bs[k1*25 + n2], tw25[m25], acc);
            m25 += k2; if (m25 >= 25) m25 -= 25;
        }
        g_C[u*1025 + k] = acc;
    }
}

__global__ void k_dft_cols(float* gnn_out, const float* __restrict__ alpha,
                           const float* __restrict__ target)
{
    __shared__ cf xs[1025], bs[1025], tw[1025], tw41[41], tw25[25];
    int tid = threadIdx.x;
    int n = blockIdx.x;
    for (int m = tid; m < 1025; m += blockDim.x){
        float ang = (float)((double)m * (2.0 * PI_D / 1025.0));
        float s, c; sincosf(ang, &s, &c);
        tw[m] = cmk(c, s);
        xs[m] = g_C[m*1025 + n];
    }
    __syncthreads();
    if (tid < 41) tw41[tid] = tw[tid*25];
    if (tid < 25) tw25[tid] = tw[tid*41];
    __syncthreads();
    for (int idx = tid; idx < 1025; idx += blockDim.x){
        int k1 = idx % 41, n2 = idx / 41;
        cf acc = cmk(0.f,0.f);
        int m41 = 0;
        for (int n1 = 0; n1 < 41; n1++){
            acc = cfma_(xs[25*n1 + n2], tw41[m41], acc);
            m41 += k1; if (m41 >= 41) m41 -= 41;
        }
        bs[k1*25 + n2] = cmul(acc, tw[n2*k1]);
    }
    __syncthreads();
    float al = alpha[0];
    const float invN2 = 1.0f / (1025.0f * 1025.0f);
    for (int k = tid; k < 1025; k += blockDim.x){
        int k1 = k % 41, k2 = k / 41;
        cf acc = cmk(0.f,0.f);
        int m25 = 0;
        for (int n2 = 0; n2 < 25; n2++){
            acc = cfma_(bs[k1*25 + n2], tw25[m25], acc);
            m25 += k2; if (m25 >= 25) m25 -= 25;
        }
        float val = sqrtf(acc.x*acc.x + acc.y*acc.y) * invN2 + al;
        int p = k*1025 + n;
        g_gnn[p]  = val;
        g_diff[p] = val - target[p];         // diff for guided-filter iter 0
        if (gnn_out) gnn_out[p] = val;
    }
}

// ---------------- Stage E: diagonal line-sum "guided filter" ----------------
__global__ void k_box1(double slope)
{
    __shared__ int lv[49];
    if (threadIdx.x < 49) lv[threadIdx.x] = (int)rint(((double)threadIdx.x - 24.0) * slope);
    __syncthreads();
    int p = blockIdx.x * blockDim.x + threadIdx.x;
    if (p >= GNN_N) return;
    int h = p / ML, w = p - h * ML;
    float acc = 0.f; int cnt = 0;
    for (int d = 0; d < 49; d++){
        int hh = h + d - 24;
        int ww = w + lv[d];
        if ((unsigned)hh < (unsigned)ML && (unsigned)ww < (unsigned)ML){
            acc += g_diff[hh*ML + ww];
            cnt++;
        }
    }
    g_tmp[p] = acc / (float)cnt;
}

__global__ void k_box2(const float* __restrict__ target, int useTarget, int writeD, double slope)
{
    __shared__ int lv[49];
    if (threadIdx.x < 49) lv[threadIdx.x] = (int)rint(((double)threadIdx.x - 24.0) * slope);
    __syncthreads();
    int p = blockIdx.x * blockDim.x + threadIdx.x;
    if (p >= GNN_N) return;
    int h = p / ML, w = p - h * ML;
    float acc = 0.f; int cnt = 0;
    for (int d = 0; d < 49; d++){
        int hh = h + d - 24;
        int ww = w + lv[d];
        if ((unsigned)hh < (unsigned)ML && (unsigned)ww < (unsigned)ML){
            acc += g_tmp[hh*ML + ww];
            cnt++;
        }
    }
    float base = useTarget ? target[p] : g_X[p];
    float xn = base + acc / (float)cnt;
    g_X[p] = xn;
    if (writeD) g_D[p]    = xn - target[p];
    else        g_diff[p] = g_gnn[p] - xn;
}

// ---------------- Stage F: reflect bilinear grid sample ---------------------
__global__ void k_grid(const float* __restrict__ coor, const float* __restrict__ thr,
                       float* __restrict__ out)
{
    int p = blockIdx.x * blockDim.x + threadIdx.x;
    if (p >= LR_N) return;
    float2 g = reinterpret_cast<const float2*>(coor)[p];
    float x = (g.x + 1.f) * 0.5f * 1024.f;
    float y = (g.y + 1.f) * 0.5f * 1024.f;
    x = fmodf(fabsf(x), 2048.f); if (x > 1024.f) x = 2048.f - x;
    y = fmodf(fabsf(y), 2048.f); if (y > 1024.f) y = 2048.f - y;
    float x0f = fminf(fmaxf(floorf(x), 0.f), 1024.f);
    float y0f = fminf(fmaxf(floorf(y), 0.f), 1024.f);
    int x0 = (int)x0f, y0 = (int)y0f;
    int x1 = min(x0 + 1, 1024), y1 = min(y0 + 1, 1024);
    float wx = x - x0f, wy = y - y0f;
    float v00 = g_D[y0*ML + x0], v01 = g_D[y0*ML + x1];
    float v10 = g_D[y1*ML + x0], v11 = g_D[y1*ML + x1];
    float v = (1.f-wy)*(1.f-wx)*v00 + (1.f-wy)*wx*v01 + wy*(1.f-wx)*v10 + wy*wx*v11;
    out[p] = v + thr[p];
}

// ---------------- launcher ---------------------------------------------------
extern "C" void kernel_launch(void* const* d_in, const int* in_sizes, int n_in,
                              void* d_out, int out_size)
{
    const float* xr     = (const float*)d_in[0];
    const float* xi     = (const float*)d_in[1];
    const float* aver_r = (const float*)d_in[2];
    const float* aver_i = (const float*)d_in[3];
    const float* target = (const float*)d_in[4];
    const float* thr    = (const float*)d_in[5];
    const float* coor   = (const float*)d_in[6];
    const float* alpha  = (const float*)d_in[7];
    const cf* fw0 = (const cf*)d_in[8];
    const cf* fb0 = (const cf*)d_in[9];
    const cf* fw1 = (const cf*)d_in[10];
    const cf* fb1 = (const cf*)d_in[11];
    const cf* lw  = (const cf*)d_in[12];
    const cf* lb  = (const cf*)d_in[13];
    const cf* gnn_w = (const cf*)d_in[14];
    const cf* ew1 = (const cf*)d_in[15];
    const cf* eb1 = (const cf*)d_in[16];
    const cf* ew2 = (const cf*)d_in[17];
    const cf* eb2 = (const cf*)d_in[18];
    const cf* lw1 = (const cf*)d_in[19];
    const cf* lb1 = (const cf*)d_in[20];
    const cf* lw2 = (const cf*)d_in[21];
    const cf* lb2 = (const cf*)d_in[22];
    const cf* mw1 = (const cf*)d_in[23];
    const cf* mb1 = (const cf*)d_in[24];
    const cf* mw2 = (const cf*)d_in[25];
    const cf* mb2 = (const cf*)d_in[26];
    const cf* mw3 = (const cf*)d_in[27];
    const cf* mb3 = (const cf*)d_in[28];
    const int* NI    = (const int*)d_in[29];
    const int* hmask = (const int*)d_in[30];
    const int* hind  = (const int*)d_in[31];

    // replicate numpy's deg/rad round-trip in double on host
    double cth[3], sth[3], slope[3];
    const double Adeg[3] = {-10.0, 0.0, 10.0};
    for (int i = 0; i < 3; i++){
        double a_rad = atan(3.0 * tan(Adeg[i] * PI_D / 180.0));
        double a_deg = a_rad * (180.0 / PI_D);
        double th    = a_deg * (PI_D / 180.0);
        cth[i] = cos(th); sth[i] = sin(th); slope[i] = tan(th);
    }

    float* outp = (float*)d_out;
    float* gnn_out = nullptr; float* lr_out = nullptr;
    if (out_size >= GNN_N + LR_N){ gnn_out = outp; lr_out = outp + GNN_N; }
    else if (out_size == LR_N)   { lr_out = outp; }
    else                         { gnn_out = outp; }

    static int smem_set = 0;
    if (!smem_set){
        cudaFuncSetAttribute(k_stageC, cudaFuncAttributeMaxDynamicSharedMemorySize, SC_SMEM);
        smem_set = 1;
    }

    k_stageA<<<(HW2 + 255)/256, 256>>>(xr, xi, fw0, fb0, fw1, fb1, lw, lb);
    k_stageB<<<(HW2 + 255)/256, 256>>>(gnn_w, NI, hmask, hind);
    k_nop<<<1, 32>>>();   // keeps k_stageC in ncu's fixed profiled launch slot
    k_stageC<<<HW2/128, 128, SC_SMEM>>>(ew1, eb1, ew2, eb2, lw1, lb1, lw2, lb2,
                                       mw1, mb1, mw2, mb2, mw3, mb3,
                                       aver_r, aver_i,
                                       (float)cth[0], (float)sth[0],
                                       (float)cth[1], (float)sth[1],
                                       (float)cth[2], (float)sth[2]);
    k_dft_rows<<<ML, 256>>>();
    k_dft_cols<<<ML, 256>>>(gnn_out, alpha, target);
    for (int i = 0; i < 3; i++){
        k_box1<<<(GNN_N + 255)/256, 256>>>(slope[i]);
        k_box2<<<(GNN_N + 255)/256, 256>>>(target, i == 0 ? 1 : 0, i == 2 ? 1 : 0, slope[i]);
    }
    if (lr_out)
        k_grid<<<(LR_N + 255)/256, 256>>>(coor, thr, lr_out);
}